// round 8
// baseline (speedup 1.0000x reference)
#include <cuda_runtime.h>

#define NN 100000
#define NE 3200000
#define IN_DIM 128
#define H1 32
#define H2 16

// Scratch (allocation-free contract: __device__ globals)
__device__ float g_inv[NN];            // deg -> 1/sqrt(deg+1)
__device__ float g_xws1[NN * H1];      // (x@W1) * inv[src]
__device__ float g_tmp1[NN * H1];      // scatter accumulator layer 1
__device__ float g_xws2[NN * H2];      // (h1@W2) * inv[src]
__device__ float g_tmp2[NN * H2];      // scatter accumulator layer 2

// ---- degree: count in-edges (self loop added as +1 later) ----
__global__ void k_deg(const int* __restrict__ dst, int E) {
    int e = blockIdx.x * blockDim.x + threadIdx.x;
    if (e < E) atomicAdd(&g_inv[dst[e]], 1.0f);
}

__global__ void k_inv(int n) {
    int i = blockIdx.x * blockDim.x + threadIdx.x;
    if (i < n) g_inv[i] = rsqrtf(g_inv[i] + 1.0f);
}

// ---- layer-1 transform: warp per node, lane = output column ----
__global__ void k_xw1(const float* __restrict__ x, const float* __restrict__ W1, int n) {
    __shared__ float Ws[IN_DIM * H1];
    for (int i = threadIdx.x; i < IN_DIM * H1; i += blockDim.x) Ws[i] = W1[i];
    __syncthreads();
    int node = (blockIdx.x * blockDim.x + threadIdx.x) >> 5;
    int lane = threadIdx.x & 31;
    if (node >= n) return;
    const float* xr = x + (size_t)node * IN_DIM;
    float xv[4];
#pragma unroll
    for (int t = 0; t < 4; t++) xv[t] = xr[t * 32 + lane];
    float acc = 0.f;
#pragma unroll
    for (int k = 0; k < IN_DIM; k++) {
        float xk = __shfl_sync(0xffffffffu, xv[k >> 5], k & 31);
        acc += xk * Ws[k * H1 + lane];
    }
    g_xws1[node * H1 + lane] = acc * g_inv[node];
}

// ---- layer-1 scatter: 8 threads per edge, float4 chunks, vector red ----
__global__ void k_scatter1(const int* __restrict__ ei, int E) {
    int t = blockIdx.x * blockDim.x + threadIdx.x;
    int e = t >> 3, c = t & 7;
    if (e >= E) return;
    int s = __ldg(&ei[e]);
    int d = __ldg(&ei[E + e]);
    float4 v = *(const float4*)&g_xws1[s * H1 + c * 4];
    float* p = &g_tmp1[d * H1 + c * 4];
    asm volatile("red.global.add.v4.f32 [%0], {%1,%2,%3,%4};"
                 :: "l"(p), "f"(v.x), "f"(v.y), "f"(v.z), "f"(v.w) : "memory");
}

// ---- finish layer 1 (scale + self-loop + bias + relu), then h1@W2, pre-scale ----
__global__ void k_l2(const float* __restrict__ b1, const float* __restrict__ W2, int n) {
    __shared__ float Ws[H1 * H2];
    for (int i = threadIdx.x; i < H1 * H2; i += blockDim.x) Ws[i] = W2[i];
    __syncthreads();
    int node = (blockIdx.x * blockDim.x + threadIdx.x) >> 5;
    int lane = threadIdx.x & 31;
    if (node >= n) return;
    float inv = g_inv[node];
    // tmp1 holds sum over non-self edges of xws1[src]; self loop adds xws1[node]
    float h = inv * (g_tmp1[node * H1 + lane] + g_xws1[node * H1 + lane]) + b1[lane];
    h = fmaxf(h, 0.f);
    float acc = 0.f;
#pragma unroll
    for (int k = 0; k < H1; k++) {
        float hk = __shfl_sync(0xffffffffu, h, k);
        acc += hk * Ws[k * H2 + (lane & 15)];
    }
    if (lane < H2) g_xws2[node * H2 + lane] = acc * inv;
}

// ---- layer-2 scatter: 4 threads per edge, float4 chunks ----
__global__ void k_scatter2(const int* __restrict__ ei, int E) {
    int t = blockIdx.x * blockDim.x + threadIdx.x;
    int e = t >> 2, c = t & 3;
    if (e >= E) return;
    int s = __ldg(&ei[e]);
    int d = __ldg(&ei[E + e]);
    float4 v = *(const float4*)&g_xws2[s * H2 + c * 4];
    float* p = &g_tmp2[d * H2 + c * 4];
    asm volatile("red.global.add.v4.f32 [%0], {%1,%2,%3,%4};"
                 :: "l"(p), "f"(v.x), "f"(v.y), "f"(v.z), "f"(v.w) : "memory");
}

// ---- epilogue: scale + self loop + bias ----
__global__ void k_out(const float* __restrict__ b2, float* __restrict__ out, int n) {
    int i = blockIdx.x * blockDim.x + threadIdx.x;
    if (i >= n * H2) return;
    int node = i / H2, j = i - node * H2;
    out[i] = g_inv[node] * (g_tmp2[i] + g_xws2[i]) + b2[j];
}

extern "C" void kernel_launch(void* const* d_in, const int* in_sizes, int n_in,
                              void* d_out, int out_size) {
    const float* x  = (const float*)d_in[0];
    const float* W1 = (const float*)d_in[1];
    const float* b1 = (const float*)d_in[2];
    const float* W2 = (const float*)d_in[3];
    const float* b2 = (const float*)d_in[4];
    const int* ei   = (const int*)d_in[5];   // int32: JAX x64 disabled
    int E = in_sizes[5] / 2;
    int n = in_sizes[0] / IN_DIM;
    float* out = (float*)d_out;

    void *p_inv, *p_t1, *p_t2;
    cudaGetSymbolAddress(&p_inv, g_inv);
    cudaGetSymbolAddress(&p_t1, g_tmp1);
    cudaGetSymbolAddress(&p_t2, g_tmp2);
    cudaMemsetAsync(p_inv, 0, (size_t)n * sizeof(float), 0);
    cudaMemsetAsync(p_t1, 0, (size_t)n * H1 * sizeof(float), 0);
    cudaMemsetAsync(p_t2, 0, (size_t)n * H2 * sizeof(float), 0);

    k_deg<<<(E + 255) / 256, 256>>>(ei + E, E);
    k_inv<<<(n + 255) / 256, 256>>>(n);
    k_xw1<<<(n * 32 + 255) / 256, 256>>>(x, W1, n);
    {
        long long nt = (long long)E * 8;
        k_scatter1<<<(unsigned)((nt + 255) / 256), 256>>>(ei, E);
    }
    k_l2<<<(n * 32 + 255) / 256, 256>>>(b1, W2, n);
    {
        long long nt = (long long)E * 4;
        k_scatter2<<<(unsigned)((nt + 255) / 256), 256>>>(ei, E);
    }
    k_out<<<(n * H2 + 255) / 256, 256>>>(b2, out, n);
}

// round 10
// speedup vs baseline: 1.1437x; 1.1437x over previous
#include <cuda_runtime.h>

#define NN 100000
#define NE 3200000
#define IN_DIM 128
#define H1 32
#define H2 16
#define CHUNK 1024
#define SCAN_T 256

// ---- scratch (__device__ globals, allocation-free contract) ----
__device__ int   g_cnt[NN];       // in-degree (no self loop)
__device__ int   g_off[NN];       // exclusive scan within chunk
__device__ int   g_bsum[128];     // per-chunk sums -> exclusive scanned
__device__ int   g_row[NN];       // CSR row start
__device__ int   g_cur[NN];       // fill cursor
__device__ float g_inv[NN];       // 1/sqrt(deg+1)
__device__ int   g_csr[NE];       // src ids grouped by dst
__device__ float g_xw1[NN * H1];  // x @ W1 (unscaled)
__device__ float g_xws2[NN * H2]; // inv[s] * (relu(h1) @ W2)

// ---- degree count ----
__global__ void k_deg(const int* __restrict__ dst, int E) {
    int e = blockIdx.x * blockDim.x + threadIdx.x;
    if (e < E) atomicAdd(&g_cnt[dst[e]], 1);
}

// ---- 2-level exclusive scan over g_cnt ----
__global__ void k_scan1(int n) {
    __shared__ int s[SCAN_T];
    int t = threadIdx.x;
    int base = blockIdx.x * CHUNK + t * 4;
    int v[4]; int sum = 0;
#pragma unroll
    for (int j = 0; j < 4; j++) { int i = base + j; v[j] = (i < n) ? g_cnt[i] : 0; sum += v[j]; }
    s[t] = sum; __syncthreads();
    for (int off = 1; off < SCAN_T; off <<= 1) {
        int x = (t >= off) ? s[t - off] : 0;
        __syncthreads();
        s[t] += x;
        __syncthreads();
    }
    int run = s[t] - sum;                 // exclusive prefix for this thread
    if (t == SCAN_T - 1) g_bsum[blockIdx.x] = s[t];
#pragma unroll
    for (int j = 0; j < 4; j++) { int i = base + j; if (i < n) g_off[i] = run; run += v[j]; }
}

__global__ void k_scan2(int nblk) {
    __shared__ int s[128];
    int t = threadIdx.x;
    int v = (t < nblk) ? g_bsum[t] : 0;
    s[t] = v; __syncthreads();
    for (int off = 1; off < 128; off <<= 1) {
        int x = (t >= off) ? s[t - off] : 0;
        __syncthreads();
        s[t] += x;
        __syncthreads();
    }
    if (t < nblk) g_bsum[t] = s[t] - v;   // exclusive
}

__global__ void k_scan3(int n) {
    int i = blockIdx.x * blockDim.x + threadIdx.x;
    if (i >= n) return;
    int row = g_off[i] + g_bsum[i >> 10];
    g_row[i] = row;
    g_cur[i] = row;
    g_inv[i] = rsqrtf((float)g_cnt[i] + 1.0f);
}

// ---- CSR fill: csr[pos] = src, grouped by dst ----
__global__ void k_fill(const int* __restrict__ ei, int E) {
    int e = blockIdx.x * blockDim.x + threadIdx.x;
    if (e >= E) return;
    int s = ei[e];
    int d = ei[E + e];
    int pos = atomicAdd(&g_cur[d], 1);
    g_csr[pos] = s;
}

// ---- layer-1 transform: warp per node (unscaled) ----
__global__ void k_xw1(const float* __restrict__ x, const float* __restrict__ W1, int n) {
    __shared__ float Ws[IN_DIM * H1];
    for (int i = threadIdx.x; i < IN_DIM * H1; i += blockDim.x) Ws[i] = W1[i];
    __syncthreads();
    int node = (blockIdx.x * blockDim.x + threadIdx.x) >> 5;
    int lane = threadIdx.x & 31;
    if (node >= n) return;
    const float* xr = x + (size_t)node * IN_DIM;
    float xv[4];
#pragma unroll
    for (int t = 0; t < 4; t++) xv[t] = xr[t * 32 + lane];
    float acc = 0.f;
#pragma unroll
    for (int k = 0; k < IN_DIM; k++) {
        float xk = __shfl_sync(0xffffffffu, xv[k >> 5], k & 31);
        acc += xk * Ws[k * H1 + lane];
    }
    g_xw1[node * H1 + lane] = acc;
}

// ---- fused: pull-aggregate layer1 + bias + relu + @W2 + inv prescale ----
__global__ void k_agg1(const float* __restrict__ b1, const float* __restrict__ W2, int n) {
    __shared__ float W2s[H1 * H2];
    __shared__ float b1s[H1];
    for (int i = threadIdx.x; i < H1 * H2; i += blockDim.x) W2s[i] = W2[i];
    if (threadIdx.x < H1) b1s[threadIdx.x] = b1[threadIdx.x];
    __syncthreads();
    int node = (blockIdx.x * blockDim.x + threadIdx.x) >> 5;
    int lane = threadIdx.x & 31;
    if (node >= n) return;
    int start = g_row[node];
    int cnt = g_cnt[node];
    int c = lane & 7, sub = lane >> 3;          // 8 lanes x 16B cover one 128B row; 4 edges in flight
    float4 acc = make_float4(0.f, 0.f, 0.f, 0.f);
    for (int i = sub; i < cnt; i += 4) {
        int s = __ldg(&g_csr[start + i]);
        float w = __ldg(&g_inv[s]);
        float4 v = *(const float4*)&g_xw1[s * H1 + c * 4];
        acc.x += w * v.x; acc.y += w * v.y; acc.z += w * v.z; acc.w += w * v.w;
    }
#pragma unroll
    for (int off = 8; off < 32; off <<= 1) {
        acc.x += __shfl_xor_sync(0xffffffffu, acc.x, off);
        acc.y += __shfl_xor_sync(0xffffffffu, acc.y, off);
        acc.z += __shfl_xor_sync(0xffffffffu, acc.z, off);
        acc.w += __shfl_xor_sync(0xffffffffu, acc.w, off);
    }
    float invd = g_inv[node];
    float4 sv = *(const float4*)&g_xw1[node * H1 + c * 4];   // self-loop message
    float h[4];
    h[0] = fmaxf(invd * (acc.x + invd * sv.x) + b1s[c * 4 + 0], 0.f);
    h[1] = fmaxf(invd * (acc.y + invd * sv.y) + b1s[c * 4 + 1], 0.f);
    h[2] = fmaxf(invd * (acc.z + invd * sv.z) + b1s[c * 4 + 2], 0.f);
    h[3] = fmaxf(invd * (acc.w + invd * sv.w) + b1s[c * 4 + 3], 0.f);
    // h1 @ W2 (redistribute h via shuffles; lanes 0..7 own col-chunks)
    int colw = lane & 15;
    float o = 0.f;
#pragma unroll
    for (int k = 0; k < H1; k++) {
        float hk = __shfl_sync(0xffffffffu, h[k & 3], k >> 2);
        o += hk * W2s[k * H2 + colw];
    }
    if (lane < H2) g_xws2[node * H2 + lane] = o * invd;
}

// ---- fused: pull-aggregate layer2 + self + bias -> out ----
__global__ void k_agg2(const float* __restrict__ b2, float* __restrict__ out, int n) {
    int node = (blockIdx.x * blockDim.x + threadIdx.x) >> 5;
    int lane = threadIdx.x & 31;
    if (node >= n) return;
    int start = g_row[node];
    int cnt = g_cnt[node];
    int c = lane & 3, sub = lane >> 2;          // 4 lanes x 16B cover one 64B row; 8 edges in flight
    float4 acc = make_float4(0.f, 0.f, 0.f, 0.f);
    for (int i = sub; i < cnt; i += 8) {
        int s = __ldg(&g_csr[start + i]);
        float4 v = *(const float4*)&g_xws2[s * H2 + c * 4];
        acc.x += v.x; acc.y += v.y; acc.z += v.z; acc.w += v.w;
    }
#pragma unroll
    for (int off = 4; off < 32; off <<= 1) {
        acc.x += __shfl_xor_sync(0xffffffffu, acc.x, off);
        acc.y += __shfl_xor_sync(0xffffffffu, acc.y, off);
        acc.z += __shfl_xor_sync(0xffffffffu, acc.z, off);
        acc.w += __shfl_xor_sync(0xffffffffu, acc.w, off);
    }
    if (lane < 4) {
        float invd = g_inv[node];
        float4 sv = *(const float4*)&g_xws2[node * H2 + c * 4];
        float4 bb = *(const float4*)&b2[c * 4];
        float4 r;
        r.x = invd * (acc.x + sv.x) + bb.x;
        r.y = invd * (acc.y + sv.y) + bb.y;
        r.z = invd * (acc.z + sv.z) + bb.z;
        r.w = invd * (acc.w + sv.w) + bb.w;
        *(float4*)&out[node * H2 + c * 4] = r;
    }
}

extern "C" void kernel_launch(void* const* d_in, const int* in_sizes, int n_in,
                              void* d_out, int out_size) {
    const float* x  = (const float*)d_in[0];
    const float* W1 = (const float*)d_in[1];
    const float* b1 = (const float*)d_in[2];
    const float* W2 = (const float*)d_in[3];
    const float* b2 = (const float*)d_in[4];
    const int* ei   = (const int*)d_in[5];     // int32 (JAX x64 disabled)
    int E = in_sizes[5] / 2;
    int n = in_sizes[0] / IN_DIM;
    float* out = (float*)d_out;

    void* p_cnt;
    cudaGetSymbolAddress(&p_cnt, g_cnt);
    cudaMemsetAsync(p_cnt, 0, (size_t)n * sizeof(int), 0);

    int nblk = (n + CHUNK - 1) / CHUNK;
    k_deg<<<(E + 255) / 256, 256>>>(ei + E, E);
    k_scan1<<<nblk, SCAN_T>>>(n);
    k_scan2<<<1, 128>>>(nblk);
    k_scan3<<<(n + 255) / 256, 256>>>(n);
    k_xw1<<<(n * 32 + 255) / 256, 256>>>(x, W1, n);
    k_fill<<<(E + 255) / 256, 256>>>(ei, E);
    k_agg1<<<(n * 32 + 255) / 256, 256>>>(b1, W2, n);
    k_agg2<<<(n * 32 + 255) / 256, 256>>>(b2, out, n);
}

// round 12
// speedup vs baseline: 1.1819x; 1.0333x over previous
#include <cuda_runtime.h>
#include <cuda_fp16.h>

#define NN 100000
#define NE 3200000
#define IN_DIM 128
#define H1 32
#define H2 16
#define CHUNK 1024
#define SCAN_T 256

// ---- scratch (__device__ globals, allocation-free contract) ----
__device__ int    g_cnt[NN];        // in-degree (no self loop)
__device__ int    g_off[NN];        // exclusive scan within chunk
__device__ int    g_bsum[128];      // per-chunk sums -> exclusive scanned
__device__ int    g_row[NN];        // CSR row start
__device__ float  g_inv[NN];        // 1/sqrt(deg+1)
__device__ int    g_pos[NE];        // per-edge slot within its dst bucket
__device__ int    g_csr[NE];        // src ids grouped by dst
__device__ __half g_xw1h[NN * H1];  // inv[s] * (x @ W1), fp16
__device__ float  g_xws2[NN * H2];  // inv[s] * (relu(h1) @ W2)

// ---- degree count; atomic return value = free CSR slot index ----
__global__ void k_deg(const int* __restrict__ dst, int E) {
    int e = blockIdx.x * blockDim.x + threadIdx.x;
    if (e < E) g_pos[e] = atomicAdd(&g_cnt[dst[e]], 1);
}

// ---- 2-level exclusive scan over g_cnt ----
__global__ void k_scan1(int n) {
    __shared__ int s[SCAN_T];
    int t = threadIdx.x;
    int base = blockIdx.x * CHUNK + t * 4;
    int v[4]; int sum = 0;
#pragma unroll
    for (int j = 0; j < 4; j++) { int i = base + j; v[j] = (i < n) ? g_cnt[i] : 0; sum += v[j]; }
    s[t] = sum; __syncthreads();
    for (int off = 1; off < SCAN_T; off <<= 1) {
        int x = (t >= off) ? s[t - off] : 0;
        __syncthreads();
        s[t] += x;
        __syncthreads();
    }
    int run = s[t] - sum;
    if (t == SCAN_T - 1) g_bsum[blockIdx.x] = s[t];
#pragma unroll
    for (int j = 0; j < 4; j++) { int i = base + j; if (i < n) g_off[i] = run; run += v[j]; }
}

__global__ void k_scan2(int nblk) {
    __shared__ int s[128];
    int t = threadIdx.x;
    int v = (t < nblk) ? g_bsum[t] : 0;
    s[t] = v; __syncthreads();
    for (int off = 1; off < 128; off <<= 1) {
        int x = (t >= off) ? s[t - off] : 0;
        __syncthreads();
        s[t] += x;
        __syncthreads();
    }
    if (t < nblk) g_bsum[t] = s[t] - v;
}

__global__ void k_scan3(int n) {
    int i = blockIdx.x * blockDim.x + threadIdx.x;
    if (i >= n) return;
    g_row[i] = g_off[i] + g_bsum[i >> 10];
    g_inv[i] = rsqrtf((float)g_cnt[i] + 1.0f);
}

// ---- CSR fill: plain store, slot precomputed by k_deg ----
__global__ void k_fill(const int* __restrict__ ei, int E) {
    int e = blockIdx.x * blockDim.x + threadIdx.x;
    if (e >= E) return;
    int d = __ldg(&ei[E + e]);
    g_csr[g_row[d] + g_pos[e]] = __ldg(&ei[e]);
}

// ---- layer-1 transform: warp per node, PRESCALED by inv, stored fp16 ----
__global__ void k_xw1(const float* __restrict__ x, const float* __restrict__ W1, int n) {
    __shared__ float Ws[IN_DIM * H1];
    for (int i = threadIdx.x; i < IN_DIM * H1; i += blockDim.x) Ws[i] = W1[i];
    __syncthreads();
    int node = (blockIdx.x * blockDim.x + threadIdx.x) >> 5;
    int lane = threadIdx.x & 31;
    if (node >= n) return;
    const float* xr = x + (size_t)node * IN_DIM;
    float xv[4];
#pragma unroll
    for (int t = 0; t < 4; t++) xv[t] = xr[t * 32 + lane];
    float acc = 0.f;
#pragma unroll
    for (int k = 0; k < IN_DIM; k++) {
        float xk = __shfl_sync(0xffffffffu, xv[k >> 5], k & 31);
        acc += xk * Ws[k * H1 + lane];
    }
    g_xw1h[node * H1 + lane] = __float2half(acc * g_inv[node]);
}

// ---- fused: pull-aggregate layer1 (fp16 rows) + bias + relu + @W2 + prescale ----
__global__ void k_agg1(const float* __restrict__ b1, const float* __restrict__ W2, int n) {
    __shared__ float W2s[H1 * H2];
    __shared__ float b1s[H1];
    for (int i = threadIdx.x; i < H1 * H2; i += blockDim.x) W2s[i] = W2[i];
    if (threadIdx.x < H1) b1s[threadIdx.x] = b1[threadIdx.x];
    __syncthreads();
    int node = (blockIdx.x * blockDim.x + threadIdx.x) >> 5;
    int lane = threadIdx.x & 31;
    if (node >= n) return;
    int start = g_row[node];
    int cnt = g_cnt[node];
    // fp16 row = 64B; 4 lanes x 16B per edge, 8 edges in flight
    int c = lane & 3, sub = lane >> 2;
    float acc[8];
#pragma unroll
    for (int j = 0; j < 8; j++) acc[j] = 0.f;
    for (int i = sub; i < cnt; i += 8) {
        int s = __ldg(&g_csr[start + i]);
        uint4 u = *(const uint4*)&g_xw1h[s * H1 + c * 8];
        float2 f0 = __half22float2(*(__half2*)&u.x);
        float2 f1 = __half22float2(*(__half2*)&u.y);
        float2 f2 = __half22float2(*(__half2*)&u.z);
        float2 f3 = __half22float2(*(__half2*)&u.w);
        acc[0] += f0.x; acc[1] += f0.y; acc[2] += f1.x; acc[3] += f1.y;
        acc[4] += f2.x; acc[5] += f2.y; acc[6] += f3.x; acc[7] += f3.y;
    }
#pragma unroll
    for (int off = 4; off < 32; off <<= 1) {
#pragma unroll
        for (int j = 0; j < 8; j++)
            acc[j] += __shfl_xor_sync(0xffffffffu, acc[j], off);
    }
    float invd = g_inv[node];
    float h[8];
    {
        // self-loop: stored self row already = invd * xw1[node]
        uint4 u = *(const uint4*)&g_xw1h[node * H1 + c * 8];
        float2 f0 = __half22float2(*(__half2*)&u.x);
        float2 f1 = __half22float2(*(__half2*)&u.y);
        float2 f2 = __half22float2(*(__half2*)&u.z);
        float2 f3 = __half22float2(*(__half2*)&u.w);
        float sv[8] = {f0.x, f0.y, f1.x, f1.y, f2.x, f2.y, f3.x, f3.y};
#pragma unroll
        for (int j = 0; j < 8; j++)
            h[j] = fmaxf(invd * (acc[j] + sv[j]) + b1s[c * 8 + j], 0.f);
    }
    // h1 @ W2: h lives 8-per-lane; source lane k>>3 owns columns (k>>3)*8+(k&7)=k
    float o = 0.f;
    int colw = lane & 15;
#pragma unroll
    for (int k = 0; k < H1; k++) {
        float hk = __shfl_sync(0xffffffffu, h[k & 7], k >> 3);
        o += hk * W2s[k * H2 + colw];
    }
    if (lane < H2) g_xws2[node * H2 + lane] = o * invd;
}

// ---- fused: pull-aggregate layer2 + self + bias -> out ----
__global__ void k_agg2(const float* __restrict__ b2, float* __restrict__ out, int n) {
    int node = (blockIdx.x * blockDim.x + threadIdx.x) >> 5;
    int lane = threadIdx.x & 31;
    if (node >= n) return;
    int start = g_row[node];
    int cnt = g_cnt[node];
    int c = lane & 3, sub = lane >> 2;   // 4 lanes x 16B per 64B row, 8 edges in flight
    float4 acc = make_float4(0.f, 0.f, 0.f, 0.f);
    for (int i = sub; i < cnt; i += 8) {
        int s = __ldg(&g_csr[start + i]);
        float4 v = *(const float4*)&g_xws2[s * H2 + c * 4];
        acc.x += v.x; acc.y += v.y; acc.z += v.z; acc.w += v.w;
    }
#pragma unroll
    for (int off = 4; off < 32; off <<= 1) {
        acc.x += __shfl_xor_sync(0xffffffffu, acc.x, off);
        acc.y += __shfl_xor_sync(0xffffffffu, acc.y, off);
        acc.z += __shfl_xor_sync(0xffffffffu, acc.z, off);
        acc.w += __shfl_xor_sync(0xffffffffu, acc.w, off);
    }
    if (lane < 4) {
        float invd = g_inv[node];
        float4 sv = *(const float4*)&g_xws2[node * H2 + c * 4];
        float4 bb = *(const float4*)&b2[c * 4];
        float4 r;
        r.x = invd * (acc.x + sv.x) + bb.x;
        r.y = invd * (acc.y + sv.y) + bb.y;
        r.z = invd * (acc.z + sv.z) + bb.z;
        r.w = invd * (acc.w + sv.w) + bb.w;
        *(float4*)&out[node * H2 + c * 4] = r;
    }
}

extern "C" void kernel_launch(void* const* d_in, const int* in_sizes, int n_in,
                              void* d_out, int out_size) {
    const float* x  = (const float*)d_in[0];
    const float* W1 = (const float*)d_in[1];
    const float* b1 = (const float*)d_in[2];
    const float* W2 = (const float*)d_in[3];
    const float* b2 = (const float*)d_in[4];
    const int* ei   = (const int*)d_in[5];   // int32 (JAX x64 disabled)
    int E = in_sizes[5] / 2;
    int n = in_sizes[0] / IN_DIM;
    float* out = (float*)d_out;

    void* p_cnt;
    cudaGetSymbolAddress(&p_cnt, g_cnt);
    cudaMemsetAsync(p_cnt, 0, (size_t)n * sizeof(int), 0);

    int nblk = (n + CHUNK - 1) / CHUNK;
    k_deg<<<(E + 255) / 256, 256>>>(ei + E, E);
    k_scan1<<<nblk, SCAN_T>>>(n);
    k_scan2<<<1, 128>>>(nblk);
    k_scan3<<<(n + 255) / 256, 256>>>(n);
    k_xw1<<<(n * 32 + 255) / 256, 256>>>(x, W1, n);
    k_fill<<<(E + 255) / 256, 256>>>(ei, E);
    k_agg1<<<(n * 32 + 255) / 256, 256>>>(b1, W2, n);
    k_agg2<<<(n * 32 + 255) / 256, 256>>>(b2, out, n);
}

// round 14
// speedup vs baseline: 1.3036x; 1.1030x over previous
#include <cuda_runtime.h>
#include <cuda_fp16.h>

#define NN 100000
#define NE 3200000
#define IN_DIM 128
#define H1 32
#define H2 16
#define CHUNK 1024
#define SCAN_T 256
#define XWB 8

// ---- scratch (__device__ globals, allocation-free contract) ----
__device__ int    g_cnt[NN];        // in-degree (no self loop)
__device__ int    g_off[NN];        // exclusive scan within chunk
__device__ int    g_bsum[128];      // per-chunk sums
__device__ int    g_row[NN];        // CSR row start
__device__ float  g_inv[NN];        // 1/sqrt(deg+1)
__device__ int    g_pos[NE];        // per-edge slot within its dst bucket
__device__ int    g_csr[NE];        // src ids grouped by dst
__device__ __half g_xw1h[NN * H1];  // inv[s] * (x @ W1), fp16
__device__ __half g_xws2h[NN * H2]; // inv[s] * (relu(h1) @ W2), fp16

// ---- degree count; atomic return value = free CSR slot index ----
__global__ void k_deg(const int* __restrict__ dst, int E) {
    int e = blockIdx.x * blockDim.x + threadIdx.x;
    if (e < E) g_pos[e] = atomicAdd(&g_cnt[dst[e]], 1);
}

// ---- level-1 scan over g_cnt (per-1024 chunk), chunk sums to g_bsum ----
__global__ void k_scan1(int n) {
    __shared__ int s[SCAN_T];
    int t = threadIdx.x;
    int base = blockIdx.x * CHUNK + t * 4;
    int v[4]; int sum = 0;
#pragma unroll
    for (int j = 0; j < 4; j++) { int i = base + j; v[j] = (i < n) ? g_cnt[i] : 0; sum += v[j]; }
    s[t] = sum; __syncthreads();
    for (int off = 1; off < SCAN_T; off <<= 1) {
        int x = (t >= off) ? s[t - off] : 0;
        __syncthreads();
        s[t] += x;
        __syncthreads();
    }
    int run = s[t] - sum;
    if (t == SCAN_T - 1) g_bsum[blockIdx.x] = s[t];
#pragma unroll
    for (int j = 0; j < 4; j++) { int i = base + j; if (i < n) g_off[i] = run; run += v[j]; }
}

// ---- level-2 scan folded in: each block re-scans chunk sums in smem ----
__global__ void k_scan3(int n, int nblk) {
    __shared__ int ps[128];
    int t = threadIdx.x;
    if (t < 128) ps[t] = (t < nblk) ? g_bsum[t] : 0;
    __syncthreads();
    for (int off = 1; off < 128; off <<= 1) {
        int v = (t < 128 && t >= off) ? ps[t - off] : 0;
        __syncthreads();
        if (t < 128) ps[t] += v;
        __syncthreads();
    }
    int i = blockIdx.x * blockDim.x + t;
    if (i < n) {
        int chunk = i >> 10;
        int pre = chunk ? ps[chunk - 1] : 0;
        g_row[i] = g_off[i] + pre;
        g_inv[i] = rsqrtf((float)g_cnt[i] + 1.0f);
    }
}

// ---- layer-1 transform: 2-warp teams, W1 held in registers, SHFL-only x bcast ----
__global__ void k_xw1(const float* __restrict__ x, const float* __restrict__ W1, int n) {
    __shared__ float part[4][XWB][32];
    int tid = threadIdx.x;
    int team = tid >> 6, wi = (tid >> 5) & 1, lane = tid & 31;
    float w[64];
#pragma unroll
    for (int j = 0; j < 64; j++)
        w[j] = __ldg(&W1[(wi * 64 + j) * H1 + lane]);
    int base = (blockIdx.x * 4 + team) * XWB;
    float accv[XWB];
#pragma unroll
    for (int b = 0; b < XWB; b++) {
        int node = base + b;
        float acc = 0.f;
        if (node < n) {
            const float* xr = x + (size_t)node * IN_DIM + wi * 64;
            float xa = xr[lane], xb = xr[32 + lane];
#pragma unroll
            for (int j = 0; j < 32; j++) {
                acc += __shfl_sync(0xffffffffu, xa, j) * w[j];
                acc += __shfl_sync(0xffffffffu, xb, j) * w[32 + j];
            }
        }
        accv[b] = acc;
    }
    if (wi == 1) {
#pragma unroll
        for (int b = 0; b < XWB; b++) part[team][b][lane] = accv[b];
    }
    asm volatile("bar.sync %0, 64;" :: "r"(team + 1) : "memory");
    if (wi == 0) {
#pragma unroll
        for (int b = 0; b < XWB; b++) {
            int node = base + b;
            if (node < n) {
                float tot = accv[b] + part[team][b][lane];
                float invd = __ldg(&g_inv[node]);
                g_xw1h[node * H1 + lane] = __float2half(tot * invd);
            }
        }
    }
}

// ---- CSR fill: plain store, slot precomputed by k_deg ----
__global__ void k_fill(const int* __restrict__ ei, int E) {
    int e = blockIdx.x * blockDim.x + threadIdx.x;
    if (e >= E) return;
    int d = __ldg(&ei[E + e]);
    g_csr[g_row[d] + g_pos[e]] = __ldg(&ei[e]);
}

// ---- fused: pull-aggregate layer1 (fp16) + bias + relu + @W2 + prescale ----
__global__ void k_agg1(const float* __restrict__ b1, const float* __restrict__ W2, int n) {
    __shared__ float W2s[H1 * H2];
    __shared__ float b1s[H1];
    for (int i = threadIdx.x; i < H1 * H2; i += blockDim.x) W2s[i] = W2[i];
    if (threadIdx.x < H1) b1s[threadIdx.x] = b1[threadIdx.x];
    __syncthreads();
    int node = (blockIdx.x * blockDim.x + threadIdx.x) >> 5;
    int lane = threadIdx.x & 31;
    if (node >= n) return;
    int start = g_row[node];
    int cnt = g_cnt[node];
    int c = lane & 3, sub = lane >> 2;    // 4 lanes x 16B per 64B row, 8 edges in flight
    float acc[8];
#pragma unroll
    for (int j = 0; j < 8; j++) acc[j] = 0.f;
    int i = sub;
    int scur = (i < cnt) ? __ldg(&g_csr[start + i]) : -1;
    while (scur >= 0) {
        int inx = i + 8;
        int snxt = (inx < cnt) ? __ldg(&g_csr[start + inx]) : -1;   // prefetch next index
        uint4 u = *(const uint4*)&g_xw1h[scur * H1 + c * 8];
        float2 f0 = __half22float2(*(__half2*)&u.x);
        float2 f1 = __half22float2(*(__half2*)&u.y);
        float2 f2 = __half22float2(*(__half2*)&u.z);
        float2 f3 = __half22float2(*(__half2*)&u.w);
        acc[0] += f0.x; acc[1] += f0.y; acc[2] += f1.x; acc[3] += f1.y;
        acc[4] += f2.x; acc[5] += f2.y; acc[6] += f3.x; acc[7] += f3.y;
        i = inx; scur = snxt;
    }
#pragma unroll
    for (int off = 4; off < 32; off <<= 1) {
#pragma unroll
        for (int j = 0; j < 8; j++)
            acc[j] += __shfl_xor_sync(0xffffffffu, acc[j], off);
    }
    float invd = g_inv[node];
    float h[8];
    {
        uint4 u = *(const uint4*)&g_xw1h[node * H1 + c * 8];  // self row (already prescaled)
        float2 f0 = __half22float2(*(__half2*)&u.x);
        float2 f1 = __half22float2(*(__half2*)&u.y);
        float2 f2 = __half22float2(*(__half2*)&u.z);
        float2 f3 = __half22float2(*(__half2*)&u.w);
        float sv[8] = {f0.x, f0.y, f1.x, f1.y, f2.x, f2.y, f3.x, f3.y};
#pragma unroll
        for (int j = 0; j < 8; j++)
            h[j] = fmaxf(invd * (acc[j] + sv[j]) + b1s[c * 8 + j], 0.f);
    }
    // h1 @ W2: source lane k>>3 owns columns (k>>3)*8+(k&7)=k
    float o = 0.f;
    int colw = lane & 15;
#pragma unroll
    for (int k = 0; k < H1; k++) {
        float hk = __shfl_sync(0xffffffffu, h[k & 7], k >> 3);
        o += hk * W2s[k * H2 + colw];
    }
    if (lane < H2) g_xws2h[node * H2 + lane] = __float2half(o * invd);
}

// ---- fused: pull-aggregate layer2 (fp16 rows, 32B) + self + bias -> out ----
__global__ void k_agg2(const float* __restrict__ b2, float* __restrict__ out, int n) {
    int node = (blockIdx.x * blockDim.x + threadIdx.x) >> 5;
    int lane = threadIdx.x & 31;
    if (node >= n) return;
    int start = g_row[node];
    int cnt = g_cnt[node];
    int c = lane & 1, sub = lane >> 1;    // 2 lanes x 16B per 32B row, 16 edges in flight
    float acc[8];
#pragma unroll
    for (int j = 0; j < 8; j++) acc[j] = 0.f;
    int i = sub;
    int scur = (i < cnt) ? __ldg(&g_csr[start + i]) : -1;
    while (scur >= 0) {
        int inx = i + 16;
        int snxt = (inx < cnt) ? __ldg(&g_csr[start + inx]) : -1;
        uint4 u = *(const uint4*)&g_xws2h[scur * H2 + c * 8];
        float2 f0 = __half22float2(*(__half2*)&u.x);
        float2 f1 = __half22float2(*(__half2*)&u.y);
        float2 f2 = __half22float2(*(__half2*)&u.z);
        float2 f3 = __half22float2(*(__half2*)&u.w);
        acc[0] += f0.x; acc[1] += f0.y; acc[2] += f1.x; acc[3] += f1.y;
        acc[4] += f2.x; acc[5] += f2.y; acc[6] += f3.x; acc[7] += f3.y;
        i = inx; scur = snxt;
    }
#pragma unroll
    for (int off = 2; off < 32; off <<= 1) {
#pragma unroll
        for (int j = 0; j < 8; j++)
            acc[j] += __shfl_xor_sync(0xffffffffu, acc[j], off);
    }
    if (lane < 2) {
        float invd = g_inv[node];
        uint4 u = *(const uint4*)&g_xws2h[node * H2 + c * 8];   // self row
        float2 f0 = __half22float2(*(__half2*)&u.x);
        float2 f1 = __half22float2(*(__half2*)&u.y);
        float2 f2 = __half22float2(*(__half2*)&u.z);
        float2 f3 = __half22float2(*(__half2*)&u.w);
        float sv[8] = {f0.x, f0.y, f1.x, f1.y, f2.x, f2.y, f3.x, f3.y};
        float4 r0, r1;
        r0.x = invd * (acc[0] + sv[0]) + b2[c * 8 + 0];
        r0.y = invd * (acc[1] + sv[1]) + b2[c * 8 + 1];
        r0.z = invd * (acc[2] + sv[2]) + b2[c * 8 + 2];
        r0.w = invd * (acc[3] + sv[3]) + b2[c * 8 + 3];
        r1.x = invd * (acc[4] + sv[4]) + b2[c * 8 + 4];
        r1.y = invd * (acc[5] + sv[5]) + b2[c * 8 + 5];
        r1.z = invd * (acc[6] + sv[6]) + b2[c * 8 + 6];
        r1.w = invd * (acc[7] + sv[7]) + b2[c * 8 + 7];
        *(float4*)&out[node * H2 + c * 8] = r0;
        *(float4*)&out[node * H2 + c * 8 + 4] = r1;
    }
}

extern "C" void kernel_launch(void* const* d_in, const int* in_sizes, int n_in,
                              void* d_out, int out_size) {
    const float* x  = (const float*)d_in[0];
    const float* W1 = (const float*)d_in[1];
    const float* b1 = (const float*)d_in[2];
    const float* W2 = (const float*)d_in[3];
    const float* b2 = (const float*)d_in[4];
    const int* ei   = (const int*)d_in[5];   // int32 (JAX x64 disabled)
    int E = in_sizes[5] / 2;
    int n = in_sizes[0] / IN_DIM;
    float* out = (float*)d_out;

    void* p_cnt;
    cudaGetSymbolAddress(&p_cnt, g_cnt);
    cudaMemsetAsync(p_cnt, 0, (size_t)n * sizeof(int), 0);

    int nblk = (n + CHUNK - 1) / CHUNK;
    k_deg<<<(E + 255) / 256, 256>>>(ei + E, E);
    k_scan1<<<nblk, SCAN_T>>>(n);
    k_scan3<<<(n + 255) / 256, 256>>>(n, nblk);
    k_xw1<<<(n + 4 * XWB - 1) / (4 * XWB), 256>>>(x, W1, n);     // 4th kernel -> profiled slot
    k_fill<<<(E + 255) / 256, 256>>>(ei, E);
    k_agg1<<<(n * 32 + 255) / 256, 256>>>(b1, W2, n);
    k_agg2<<<(n * 32 + 255) / 256, 256>>>(b2, out, n);
}

// round 17
// speedup vs baseline: 1.6692x; 1.2805x over previous
#include <cuda_runtime.h>
#include <cuda_fp16.h>

#define NN 100000
#define NE 3200000
#define IN_DIM 128
#define H1 32
#define H2 16
#define CHUNK 1024
#define SCAN_T 256

// ---- scratch (__device__ globals, allocation-free contract) ----
__device__ int    g_cnt[NN];        // in-degree (no self loop)
__device__ int    g_off[NN];        // exclusive scan within chunk
__device__ int    g_bsum[128];      // per-chunk sums
__device__ int    g_row[NN];        // CSR row start
__device__ float  g_inv[NN];        // 1/sqrt(deg+1)
__device__ int    g_pos[NE];        // per-edge slot within its dst bucket
__device__ int    g_csr[NE];        // src ids grouped by dst
__device__ __half g_xw1h[NN * H1];  // inv[s] * (x @ W1), fp16
__device__ __half g_xws2h[NN * H2]; // inv[s] * (relu(h1) @ W2), fp16

// ---- degree count; atomic return value = free CSR slot index ----
__global__ void k_deg(const int* __restrict__ dst, int E) {
    int e = blockIdx.x * blockDim.x + threadIdx.x;
    if (e < E) g_pos[e] = atomicAdd(&g_cnt[dst[e]], 1);
}

// ---- level-1 scan over g_cnt (per-1024 chunk), chunk sums to g_bsum ----
__global__ void k_scan1(int n) {
    __shared__ int s[SCAN_T];
    int t = threadIdx.x;
    int base = blockIdx.x * CHUNK + t * 4;
    int v[4]; int sum = 0;
#pragma unroll
    for (int j = 0; j < 4; j++) { int i = base + j; v[j] = (i < n) ? g_cnt[i] : 0; sum += v[j]; }
    s[t] = sum; __syncthreads();
    for (int off = 1; off < SCAN_T; off <<= 1) {
        int x = (t >= off) ? s[t - off] : 0;
        __syncthreads();
        s[t] += x;
        __syncthreads();
    }
    int run = s[t] - sum;
    if (t == SCAN_T - 1) g_bsum[blockIdx.x] = s[t];
#pragma unroll
    for (int j = 0; j < 4; j++) { int i = base + j; if (i < n) g_off[i] = run; run += v[j]; }
}

// ---- level-2 scan folded in: each block re-scans chunk sums in smem ----
__global__ void k_scan3(int n, int nblk) {
    __shared__ int ps[128];
    int t = threadIdx.x;
    if (t < 128) ps[t] = (t < nblk) ? g_bsum[t] : 0;
    __syncthreads();
    for (int off = 1; off < 128; off <<= 1) {
        int v = (t < 128 && t >= off) ? ps[t - off] : 0;
        __syncthreads();
        if (t < 128) ps[t] += v;
        __syncthreads();
    }
    int i = blockIdx.x * blockDim.x + t;
    if (i < n) {
        int chunk = i >> 10;
        int pre = chunk ? ps[chunk - 1] : 0;
        g_row[i] = g_off[i] + pre;
        g_inv[i] = rsqrtf((float)g_cnt[i] + 1.0f);
    }
}

// ---- layer-1 transform on tensor cores: mma.m16n8k8.tf32 ----
// Block: 256 thr = 8 warps x 16 nodes = 128 nodes/block. W1 in smem, pad 40.
__global__ void k_xw1(const float* __restrict__ x, const float* __restrict__ W1, int n) {
    __shared__ float Ws[IN_DIM * 40];
    int tid = threadIdx.x;
    for (int e = tid; e < IN_DIM * H1; e += 256)
        Ws[(e >> 5) * 40 + (e & 31)] = W1[e];
    __syncthreads();
    int warp = tid >> 5, lane = tid & 31;
    int base = blockIdx.x * 128 + warp * 16;
    if (base >= n) return;                 // n % 16 == 0: full tiles only
    int g = lane >> 2, t = lane & 3;
    float c[4][4];
#pragma unroll
    for (int nt = 0; nt < 4; nt++)
#pragma unroll
        for (int j = 0; j < 4; j++) c[nt][j] = 0.f;
    const float* xr0 = x + (size_t)(base + g) * IN_DIM;
    const float* xr1 = x + (size_t)(base + 8 + g) * IN_DIM;
#pragma unroll
    for (int ks = 0; ks < 16; ks++) {
        int k0 = ks * 8 + t;
        float f0 = __ldg(&xr0[k0]);
        float f1 = __ldg(&xr1[k0]);
        float f2 = __ldg(&xr0[k0 + 4]);
        float f3 = __ldg(&xr1[k0 + 4]);
        unsigned a0, a1, a2, a3;
        asm("cvt.rna.tf32.f32 %0, %1;" : "=r"(a0) : "f"(f0));
        asm("cvt.rna.tf32.f32 %0, %1;" : "=r"(a1) : "f"(f1));
        asm("cvt.rna.tf32.f32 %0, %1;" : "=r"(a2) : "f"(f2));
        asm("cvt.rna.tf32.f32 %0, %1;" : "=r"(a3) : "f"(f3));
#pragma unroll
        for (int nt = 0; nt < 4; nt++) {
            float b0f = Ws[k0 * 40 + nt * 8 + g];
            float b1f = Ws[(k0 + 4) * 40 + nt * 8 + g];
            unsigned b0, b1;
            asm("cvt.rna.tf32.f32 %0, %1;" : "=r"(b0) : "f"(b0f));
            asm("cvt.rna.tf32.f32 %0, %1;" : "=r"(b1) : "f"(b1f));
            asm("mma.sync.aligned.m16n8k8.row.col.f32.tf32.tf32.f32 "
                "{%0,%1,%2,%3}, {%4,%5,%6,%7}, {%8,%9}, {%0,%1,%2,%3};"
                : "+f"(c[nt][0]), "+f"(c[nt][1]), "+f"(c[nt][2]), "+f"(c[nt][3])
                : "r"(a0), "r"(a1), "r"(a2), "r"(a3), "r"(b0), "r"(b1));
        }
    }
    float invr0 = __ldg(&g_inv[base + g]);
    float invr1 = __ldg(&g_inv[base + 8 + g]);
#pragma unroll
    for (int nt = 0; nt < 4; nt++) {
        int col = nt * 8 + 2 * t;
        __half2 h0 = __floats2half2_rn(c[nt][0] * invr0, c[nt][1] * invr0);
        __half2 h1 = __floats2half2_rn(c[nt][2] * invr1, c[nt][3] * invr1);
        *(__half2*)&g_xw1h[(base + g) * H1 + col] = h0;
        *(__half2*)&g_xw1h[(base + 8 + g) * H1 + col] = h1;
    }
}

// ---- CSR fill: plain store, slot precomputed by k_deg ----
__global__ void k_fill(const int* __restrict__ ei, int E) {
    int e = blockIdx.x * blockDim.x + threadIdx.x;
    if (e >= E) return;
    int d = __ldg(&ei[E + e]);
    g_csr[g_row[d] + g_pos[e]] = __ldg(&ei[e]);
}

// ---- fused: pull-aggregate layer1 (fp16) + bias + relu + @W2 + prescale ----
__global__ void k_agg1(const float* __restrict__ b1, const float* __restrict__ W2, int n) {
    __shared__ float W2s[H1 * H2];
    __shared__ float b1s[H1];
    for (int i = threadIdx.x; i < H1 * H2; i += blockDim.x) W2s[i] = W2[i];
    if (threadIdx.x < H1) b1s[threadIdx.x] = b1[threadIdx.x];
    __syncthreads();
    int node = (blockIdx.x * blockDim.x + threadIdx.x) >> 5;
    int lane = threadIdx.x & 31;
    if (node >= n) return;
    int start = g_row[node];
    int cnt = g_cnt[node];
    int c = lane & 3, sub = lane >> 2;    // 4 lanes x 16B per 64B row, 8 edges in flight
    float acc[8];
#pragma unroll
    for (int j = 0; j < 8; j++) acc[j] = 0.f;
    int i = sub;
    int scur = (i < cnt) ? __ldg(&g_csr[start + i]) : -1;
    while (scur >= 0) {
        int inx = i + 8;
        int snxt = (inx < cnt) ? __ldg(&g_csr[start + inx]) : -1;   // prefetch next index
        uint4 u = *(const uint4*)&g_xw1h[scur * H1 + c * 8];
        float2 f0 = __half22float2(*(__half2*)&u.x);
        float2 f1 = __half22float2(*(__half2*)&u.y);
        float2 f2 = __half22float2(*(__half2*)&u.z);
        float2 f3 = __half22float2(*(__half2*)&u.w);
        acc[0] += f0.x; acc[1] += f0.y; acc[2] += f1.x; acc[3] += f1.y;
        acc[4] += f2.x; acc[5] += f2.y; acc[6] += f3.x; acc[7] += f3.y;
        i = inx; scur = snxt;
    }
#pragma unroll
    for (int off = 4; off < 32; off <<= 1) {
#pragma unroll
        for (int j = 0; j < 8; j++)
            acc[j] += __shfl_xor_sync(0xffffffffu, acc[j], off);
    }
    float invd = g_inv[node];
    float h[8];
    {
        uint4 u = *(const uint4*)&g_xw1h[node * H1 + c * 8];  // self row (already prescaled)
        float2 f0 = __half22float2(*(__half2*)&u.x);
        float2 f1 = __half22float2(*(__half2*)&u.y);
        float2 f2 = __half22float2(*(__half2*)&u.z);
        float2 f3 = __half22float2(*(__half2*)&u.w);
        float sv[8] = {f0.x, f0.y, f1.x, f1.y, f2.x, f2.y, f3.x, f3.y};
#pragma unroll
        for (int j = 0; j < 8; j++)
            h[j] = fmaxf(invd * (acc[j] + sv[j]) + b1s[c * 8 + j], 0.f);
    }
    // h1 @ W2: source lane k>>3 owns columns (k>>3)*8+(k&7)=k
    float o = 0.f;
    int colw = lane & 15;
#pragma unroll
    for (int k = 0; k < H1; k++) {
        float hk = __shfl_sync(0xffffffffu, h[k & 7], k >> 3);
        o += hk * W2s[k * H2 + colw];
    }
    if (lane < H2) g_xws2h[node * H2 + lane] = __float2half(o * invd);
}

// ---- fused: pull-aggregate layer2 (fp16 rows, 32B) + self + bias -> out ----
__global__ void k_agg2(const float* __restrict__ b2, float* __restrict__ out, int n) {
    int node = (blockIdx.x * blockDim.x + threadIdx.x) >> 5;
    int lane = threadIdx.x & 31;
    if (node >= n) return;
    int start = g_row[node];
    int cnt = g_cnt[node];
    int c = lane & 1, sub = lane >> 1;    // 2 lanes x 16B per 32B row, 16 edges in flight
    float acc[8];
#pragma unroll
    for (int j = 0; j < 8; j++) acc[j] = 0.f;
    int i = sub;
    int scur = (i < cnt) ? __ldg(&g_csr[start + i]) : -1;
    while (scur >= 0) {
        int inx = i + 16;
        int snxt = (inx < cnt) ? __ldg(&g_csr[start + inx]) : -1;
        uint4 u = *(const uint4*)&g_xws2h[scur * H2 + c * 8];
        float2 f0 = __half22float2(*(__half2*)&u.x);
        float2 f1 = __half22float2(*(__half2*)&u.y);
        float2 f2 = __half22float2(*(__half2*)&u.z);
        float2 f3 = __half22float2(*(__half2*)&u.w);
        acc[0] += f0.x; acc[1] += f0.y; acc[2] += f1.x; acc[3] += f1.y;
        acc[4] += f2.x; acc[5] += f2.y; acc[6] += f3.x; acc[7] += f3.y;
        i = inx; scur = snxt;
    }
#pragma unroll
    for (int off = 2; off < 32; off <<= 1) {
#pragma unroll
        for (int j = 0; j < 8; j++)
            acc[j] += __shfl_xor_sync(0xffffffffu, acc[j], off);
    }
    if (lane < 2) {
        float invd = g_inv[node];
        uint4 u = *(const uint4*)&g_xws2h[node * H2 + c * 8];   // self row
        float2 f0 = __half22float2(*(__half2*)&u.x);
        float2 f1 = __half22float2(*(__half2*)&u.y);
        float2 f2 = __half22float2(*(__half2*)&u.z);
        float2 f3 = __half22float2(*(__half2*)&u.w);
        float sv[8] = {f0.x, f0.y, f1.x, f1.y, f2.x, f2.y, f3.x, f3.y};
        float4 r0, r1;
        r0.x = invd * (acc[0] + sv[0]) + b2[c * 8 + 0];
        r0.y = invd * (acc[1] + sv[1]) + b2[c * 8 + 1];
        r0.z = invd * (acc[2] + sv[2]) + b2[c * 8 + 2];
        r0.w = invd * (acc[3] + sv[3]) + b2[c * 8 + 3];
        r1.x = invd * (acc[4] + sv[4]) + b2[c * 8 + 4];
        r1.y = invd * (acc[5] + sv[5]) + b2[c * 8 + 5];
        r1.z = invd * (acc[6] + sv[6]) + b2[c * 8 + 6];
        r1.w = invd * (acc[7] + sv[7]) + b2[c * 8 + 7];
        *(float4*)&out[node * H2 + c * 8] = r0;
        *(float4*)&out[node * H2 + c * 8 + 4] = r1;
    }
}

extern "C" void kernel_launch(void* const* d_in, const int* in_sizes, int n_in,
                              void* d_out, int out_size) {
    const float* x  = (const float*)d_in[0];
    const float* W1 = (const float*)d_in[1];
    const float* b1 = (const float*)d_in[2];
    const float* W2 = (const float*)d_in[3];
    const float* b2 = (const float*)d_in[4];
    const int* ei   = (const int*)d_in[5];   // int32 (JAX x64 disabled)
    int E = in_sizes[5] / 2;
    int n = in_sizes[0] / IN_DIM;
    float* out = (float*)d_out;

    void* p_cnt;
    cudaGetSymbolAddress(&p_cnt, g_cnt);
    cudaMemsetAsync(p_cnt, 0, (size_t)n * sizeof(int), 0);

    int nblk = (n + CHUNK - 1) / CHUNK;
    k_deg<<<(E + 255) / 256, 256>>>(ei + E, E);
    k_scan1<<<nblk, SCAN_T>>>(n);
    k_scan3<<<(n + 255) / 256, 256>>>(n, nblk);
    k_xw1<<<(n + 127) / 128, 256>>>(x, W1, n);   // 4th kernel -> profiled slot
    k_fill<<<(E + 255) / 256, 256>>>(ei, E);
    k_agg1<<<(n * 32 + 255) / 256, 256>>>(b1, W2, n);
    k_agg2<<<(n * 32 + 255) / 256, 256>>>(b2, out, n);
}